// round 16
// baseline (speedup 1.0000x reference)
#include <cuda_runtime.h>
#include <cuda_fp16.h>
#include <cstdint>

#define BATCH 4096
#define IN    2048
#define HID   8192
#define NCLS  1000
#define KH    2048          // hi-only K
#define NCH   32            // KH / 64 k-chunks
#define ST    2             // pipeline stages (2 CTAs/SM provide the overlap)
#define STAGE_BYTES 49152u  // A 32KB + B 16KB
#define MARGIN 3.0f         // covers fp16-accum error with ~10x slack (validated R7)
#define MAXCAND 64

// ---------------- scratch (static device arrays; no allocation) -------------
__device__ __align__(128) __half g_X[(size_t)BATCH * KH];    // hi(x)   [B, KH]
__device__ __align__(128) __half g_W[(size_t)HID   * KH];    // hi(Wk)  [HID, KH]
__device__ __align__(128) __half g_C[(size_t)BATCH * HID];   // approx scores, fp16
__device__ __align__(128) unsigned g_rowmax[BATCH];          // ordered-uint row max
__device__ __align__(128) unsigned g_tmax[(size_t)BATCH * 64]; // per (row, 128-col tile) max
__device__ __align__(128) float  g_WgT[(size_t)HID * NCLS];  // Wg transposed

// ---------------- helpers ----------------------------------------------------
__device__ __forceinline__ uint32_t smem_u32(const void* p) {
    uint32_t a;
    asm("{ .reg .u64 t; cvta.to.shared.u64 t, %1; cvt.u32.u64 %0, t; }" : "=r"(a) : "l"(p));
    return a;
}
__device__ __forceinline__ void cp_async16(uint32_t dst, const void* src) {
    asm volatile("cp.async.cg.shared.global [%0], [%1], 16;" :: "r"(dst), "l"(src));
}
#define CP_COMMIT() asm volatile("cp.async.commit_group;" ::: "memory")
#define CP_WAIT(n)  asm volatile("cp.async.wait_group %0;" :: "n"(n) : "memory")

#define LDSM4(r0, r1, r2, r3, a)                                             \
    asm volatile("ldmatrix.sync.aligned.m8n8.x4.shared.b16 {%0,%1,%2,%3}, [%4];" \
                 : "=r"(r0), "=r"(r1), "=r"(r2), "=r"(r3) : "r"(a))

// fp16-accumulate MMA
__device__ __forceinline__ void mma16816_f16(uint32_t* c, const uint32_t* a, const uint32_t* b) {
    asm volatile(
        "mma.sync.aligned.m16n8k16.row.col.f16.f16.f16.f16 "
        "{%0,%1}, {%2,%3,%4,%5}, {%6,%7}, {%0,%1};"
        : "+r"(c[0]), "+r"(c[1])
        : "r"(a[0]), "r"(a[1]), "r"(a[2]), "r"(a[3]), "r"(b[0]), "r"(b[1]));
}

__device__ __forceinline__ uint32_t sw128(uint32_t off) { return off ^ ((off >> 3) & 0x70); }

// order-preserving float<->uint
__device__ __forceinline__ unsigned fmap(float v) {
    unsigned b = __float_as_uint(v);
    return (b & 0x80000000u) ? ~b : (b | 0x80000000u);
}
__device__ __forceinline__ float funmap(unsigned m) {
    unsigned b = (m & 0x80000000u) ? (m & 0x7FFFFFFFu) : ~m;
    return __uint_as_float(b);
}

// ---------------- prep: convert x/W to fp16 + init rowmax ----------------------
#define NBX ((BATCH * KH / 4) / 256)          // 8192
#define NBW ((HID * KH / 4) / 256)            // 16384
__global__ __launch_bounds__(256)
void prep_kernel(const float* __restrict__ x, const float* __restrict__ Wk) {
    const int bid = blockIdx.x;
    const int tid = threadIdx.x;
    if (bid < NBX) {
        int i = bid * 256 + tid;
        if (i < BATCH) g_rowmax[i] = 0u;            // == -inf in mapped space
        float4 v = ((const float4*)x)[i];
        __half2 h0 = __floats2half2_rn(v.x, v.y);
        __half2 h1 = __floats2half2_rn(v.z, v.w);
        ((uint2*)g_X)[i] = make_uint2(*(unsigned*)&h0, *(unsigned*)&h1);
    } else {
        int i = (bid - NBX) * 256 + tid;
        float4 v = ((const float4*)Wk)[i];
        __half2 h0 = __floats2half2_rn(v.x, v.y);
        __half2 h1 = __floats2half2_rn(v.z, v.w);
        ((uint2*)g_W)[i] = make_uint2(*(unsigned*)&h0, *(unsigned*)&h1);
    }
}

// ---------------- Wg transpose (runs on side stream, overlapped with GEMM) -----
__global__ __launch_bounds__(256)
void transpose_wg_kernel(const float* __restrict__ Wg) {
    __shared__ float t[32][33];
    const int tb  = blockIdx.x;
    const int tid = threadIdx.x;
    int h0  = (tb & 255) * 32;          // HID/32 = 256
    int c0  = (tb >> 8) * 32;
    int txx = tid & 31, ty = tid >> 5;  // ty: 0..7
#pragma unroll
    for (int r = 0; r < 4; r++) {
        int c = c0 + ty + r * 8;
        if (c < NCLS) t[ty + r * 8][txx] = Wg[(size_t)c * HID + h0 + txx];
    }
    __syncthreads();
#pragma unroll
    for (int r = 0; r < 4; r++) {
        int ho = h0 + ty + r * 8, co = c0 + txx;
        if (co < NCLS) g_WgT[(size_t)ho * NCLS + co] = t[txx][ty + r * 8];
    }
}

// ---------------- pass 1: fp16 GEMM + fused row/tile max -----------------------
// CTA tile 256x128, 8 warps 4(m)x2(n), warp tile 64x64, 2-stage cp.async,
// 2 CTAs/SM, ONE barrier per chunk.
__global__ __launch_bounds__(256, 2)
void gemm_approx() {
    extern __shared__ char smem[];
    const int tid  = threadIdx.x;
    const int lane = tid & 31;
    const int wid  = tid >> 5;
    const int warp_m = wid >> 1;  // 0..3
    const int warp_n = wid & 1;   // 0..1

    int bid = blockIdx.x;
    int group = bid >> 7, within = bid & 127;
    int ncol = (group << 3) | (within & 7);   // 0..63
    int mrow = within >> 3;                   // 0..15
    const int bm0 = mrow * 256;
    const int bn0 = ncol * 128;

    uint32_t sb    = smem_u32(smem);
    uint32_t tiles = (sb + 1023) & ~1023u;

    const int row_l = tid >> 3;
    const int colb  = (tid & 7) * 16;
    uint32_t dswA[8];
#pragma unroll
    for (int i = 0; i < 8; i++) dswA[i] = sw128((row_l + 32 * i) * 128 + colb);

    const __half* pA = g_X + (size_t)(bm0 + row_l) * KH + (colb >> 1);
    const __half* pB = g_W + (size_t)(bn0 + row_l) * KH + (colb >> 1);

    const uint32_t aRow = warp_m * 64 + (lane & 15);
    const uint32_t aCol = (lane >> 4) << 4;
    const uint32_t bRow = warp_n * 64 + (lane & 7) + ((lane >> 4) << 3);
    const uint32_t bCol = ((lane >> 3) & 1) << 4;
    uint32_t aSwk[4], bSwk[4];
#pragma unroll
    for (int kk = 0; kk < 4; kk++) {
        aSwk[kk] = sw128(aRow * 128 + aCol + kk * 32);
        bSwk[kk] = sw128(bRow * 128 + bCol + kk * 32);
    }

    uint32_t acc[4][8][2];   // fp16x2 accumulators
#pragma unroll
    for (int i = 0; i < 4; i++)
#pragma unroll
        for (int j = 0; j < 8; j++) { acc[i][j][0] = 0u; acc[i][j][1] = 0u; }

    // prologue: issue chunk 0
    {
        uint32_t As = tiles;
        uint32_t Bs = As + 32768u;
#pragma unroll
        for (int i = 0; i < 8; i++) cp_async16(As + dswA[i], pA + (size_t)i * 32 * KH);
#pragma unroll
        for (int i = 0; i < 4; i++) cp_async16(Bs + dswA[i], pB + (size_t)i * 32 * KH);
        CP_COMMIT();
    }

    for (int c = 0; c < NCH; c++) {
        const int s = c & 1;

        CP_WAIT(0);
        __syncthreads();   // chunk c visible; all warps done with chunk c-1 (stage s^1)

        if (c + 1 < NCH) {
            uint32_t As = tiles + (s ^ 1) * STAGE_BYTES;
            uint32_t Bs = As + 32768u;
            size_t ko = (size_t)(c + 1) * 64;
#pragma unroll
            for (int i = 0; i < 8; i++) cp_async16(As + dswA[i], pA + (size_t)i * 32 * KH + ko);
#pragma unroll
            for (int i = 0; i < 4; i++) cp_async16(Bs + dswA[i], pB + (size_t)i * 32 * KH + ko);
            CP_COMMIT();
        }

        const uint32_t aBase = tiles + s * STAGE_BYTES;
        const uint32_t bBase = aBase + 32768u;

#pragma unroll
        for (int kk = 0; kk < 4; kk++) {
            uint32_t a[4][4];
#pragma unroll
            for (int im = 0; im < 4; im++)
                LDSM4(a[im][0], a[im][1], a[im][2], a[im][3],
                      aBase + aSwk[kk] + im * 2048u);
            uint32_t b[8][2];
#pragma unroll
            for (int in2 = 0; in2 < 4; in2++) {
                uint32_t r0, r1, r2, r3;
                LDSM4(r0, r1, r2, r3, bBase + bSwk[kk] + in2 * 2048u);
                b[2 * in2][0] = r0;     b[2 * in2][1] = r1;
                b[2 * in2 + 1][0] = r2; b[2 * in2 + 1][1] = r3;
            }
#pragma unroll
            for (int im = 0; im < 4; im++)
#pragma unroll
                for (int jn = 0; jn < 8; jn++)
                    mma16816_f16(acc[im][jn], a[im], b[jn]);
        }
        // no trailing sync: next iteration's top sync orders stage reuse
    }

    // ---- epilogue: store C + fused per-row / per-tile max ----
    __syncthreads();                       // all compute done; smem reusable
    unsigned* rmax = (unsigned*)smem;      // [256] per-CTA row maxima
    rmax[tid] = 0u;
    __syncthreads();

#pragma unroll
    for (int im = 0; im < 4; im++) {
        int rloc = warp_m * 64 + im * 16 + (lane >> 2);
        int r0 = bm0 + rloc;
        float m0 = -3.4e38f, m1 = -3.4e38f;
#pragma unroll
        for (int jn = 0; jn < 8; jn++) {
            int col = bn0 + warp_n * 64 + jn * 8 + (lane & 3) * 2;
            *(uint32_t*)&g_C[(size_t)r0 * HID + col]       = acc[im][jn][0];
            *(uint32_t*)&g_C[(size_t)(r0 + 8) * HID + col] = acc[im][jn][1];
            __half2 h0 = *(__half2*)&acc[im][jn][0];
            __half2 h1 = *(__half2*)&acc[im][jn][1];
            m0 = fmaxf(m0, fmaxf(__low2float(h0), __high2float(h0)));
            m1 = fmaxf(m1, fmaxf(__low2float(h1), __high2float(h1)));
        }
        atomicMax(&rmax[rloc],     fmap(m0));
        atomicMax(&rmax[rloc + 8], fmap(m1));
    }
    __syncthreads();
    // this CTA is the exclusive owner of (rows bm0..bm0+255, tile ncol)
    g_tmax[(size_t)(bm0 + tid) * 64 + ncol] = rmax[tid];
    atomicMax(&g_rowmax[bm0 + tid], rmax[tid]);
}

// ---------------- pass 2: screen + exact refine + fused output gather ----------
__global__ __launch_bounds__(256)
void refine_kernel(const float* __restrict__ x, const float* __restrict__ Wk,
                   float* __restrict__ out) {
    __shared__ float4 xs4[IN / 4];    // 8KB: row of x
    __shared__ float red8[8];
    __shared__ float tot_s;
    __shared__ int   cand[MAXCAND];
    __shared__ int   tlist[64];
    __shared__ int   ncand, ntl, best_s;

    const int b    = blockIdx.x;
    const int tid  = threadIdx.x;
    const int lane = tid & 31;
    const int wid  = tid >> 5;

    if (tid == 0) { ncand = 0; ntl = 0; }
    const float4* xrow = (const float4*)(x + (size_t)b * IN);
    for (int i = tid; i < IN / 4; i += 256) xs4[i] = xrow[i];

    const float thr = funmap(g_rowmax[b]) - MARGIN;
    __syncthreads();

    // screen 64 tile maxima
    if (tid < 64) {
        if (funmap(g_tmax[(size_t)b * 64 + tid]) >= thr) {
            int p = atomicAdd(&ntl, 1);
            tlist[p] = tid;
        }
    }
    __syncthreads();
    const int nt = ntl;

    // scan only promising tiles for candidate columns
    for (int ti = 0; ti < nt; ti++) {
        const int t = tlist[ti];
        if (tid < 64) {
            __half2 v = *(const __half2*)(g_C + (size_t)b * HID + t * 128 + 2 * tid);
            float a = __low2float(v), c = __high2float(v);
            if (a >= thr) { int p = atomicAdd(&ncand, 1); if (p < MAXCAND) cand[p] = t * 128 + 2 * tid; }
            if (c >= thr) { int p = atomicAdd(&ncand, 1); if (p < MAXCAND) cand[p] = t * 128 + 2 * tid + 1; }
        }
    }
    __syncthreads();
    const int nc = min(ncand, MAXCAND);

    // block-wide exact fp32 dot per candidate (nc is typically 1-2)
    float bestv = -3.4e38f;
    int   besti = HID;
    for (int ci = 0; ci < nc; ci++) {
        const int h = cand[ci];
        const float4* wr = (const float4*)(Wk + (size_t)h * IN);
        float p = 0.0f;
        for (int k = tid; k < IN / 4; k += 256) {
            float4 xv = xs4[k], wv = wr[k];
            p = fmaf(xv.x, wv.x, p); p = fmaf(xv.y, wv.y, p);
            p = fmaf(xv.z, wv.z, p); p = fmaf(xv.w, wv.w, p);
        }
#pragma unroll
        for (int o = 16; o > 0; o >>= 1) p += __shfl_xor_sync(0xffffffffu, p, o);
        if (lane == 0) red8[wid] = p;
        __syncthreads();
        if (tid == 0) {
            float t = 0.0f;
#pragma unroll
            for (int i = 0; i < 8; i++) t += red8[i];
            tot_s = t;
        }
        __syncthreads();
        float tot = tot_s;
        if (tot > bestv || (tot == bestv && h < besti)) { bestv = tot; besti = h; }
        __syncthreads();   // red8/tot_s reuse
    }
    if (tid == 0) best_s = besti;
    __syncthreads();

    // fused output gather: out[b][:] = WgT[besti][:]  (4000B rows, 16B aligned)
    const float4* src = (const float4*)(g_WgT + (size_t)best_s * NCLS);
    float4* dst = (float4*)(out + (size_t)b * NCLS);
    for (int c = tid; c < NCLS / 4; c += 256) dst[c] = src[c];
}

// ---------------- launch --------------------------------------------------------
extern "C" void kernel_launch(void* const* d_in, const int* in_sizes, int n_in,
                              void* d_out, int out_size) {
    const float* x  = (const float*)d_in[0];   // [BATCH, IN]
    const float* Wk = (const float*)d_in[1];   // [HID, IN]
    const float* Wg = (const float*)d_in[2];   // [NCLS, HID]
    float* out = (float*)d_out;                // [BATCH, NCLS]

    // lazily-created side stream + events (host objects, no device memory)
    static cudaStream_t s2 = nullptr;
    static cudaEvent_t evFork = nullptr, evJoin = nullptr;
    if (!s2) {
        cudaStreamCreateWithFlags(&s2, cudaStreamNonBlocking);
        cudaEventCreateWithFlags(&evFork, cudaEventDisableTiming);
        cudaEventCreateWithFlags(&evJoin, cudaEventDisableTiming);
    }

    const int SMEM_BYTES = 1024 + ST * (int)STAGE_BYTES;   // ~97KB per CTA
    cudaFuncSetAttribute(gemm_approx, cudaFuncAttributeMaxDynamicSharedMemorySize, SMEM_BYTES);

    // fork: Wg transpose runs on s2, overlapped with prep+GEMM (independent data)
    cudaEventRecord(evFork, 0);
    cudaStreamWaitEvent(s2, evFork, 0);
    transpose_wg_kernel<<<(HID / 32) * ((NCLS + 31) / 32), 256, 0, s2>>>(Wg);
    cudaEventRecord(evJoin, s2);

    prep_kernel<<<NBX + NBW, 256>>>(x, Wk);

    gemm_approx<<<(BATCH / 256) * (HID / 128), 256, SMEM_BYTES>>>();

    // join: refine reads g_WgT
    cudaStreamWaitEvent(0, evJoin, 0);
    refine_kernel<<<BATCH, 256>>>(x, Wk, out);
}

// round 17
// speedup vs baseline: 1.0321x; 1.0321x over previous
#include <cuda_runtime.h>
#include <cuda_fp16.h>
#include <cstdint>

#define BATCH 4096
#define IN    2048
#define HID   8192
#define NCLS  1000
#define KH    2048          // hi-only K
#define NCH   32            // KH / 64 k-chunks
#define ST    2             // pipeline stages (2 CTAs/SM provide the overlap)
#define STAGE_BYTES 49152u  // A 32KB + B 16KB
#define MARGIN 3.0f         // covers fp16-accum error with ~10x slack (validated R7)
#define MAXCAND 64

// ---------------- scratch (static device arrays; no allocation) -------------
__device__ __align__(128) __half g_X[(size_t)BATCH * KH];    // hi(x)   [B, KH]
__device__ __align__(128) __half g_W[(size_t)HID   * KH];    // hi(Wk)  [HID, KH]
__device__ __align__(128) __half g_C[(size_t)BATCH * HID];   // approx scores, fp16
__device__ __align__(128) unsigned g_rowmax[BATCH];          // ordered-uint row max
__device__ __align__(128) unsigned g_tmax[(size_t)BATCH * 64]; // per (row, 128-col tile) max
__device__ __align__(128) float  g_WgT[(size_t)HID * NCLS];  // Wg transposed

// ---------------- helpers ----------------------------------------------------
__device__ __forceinline__ uint32_t smem_u32(const void* p) {
    uint32_t a;
    asm("{ .reg .u64 t; cvta.to.shared.u64 t, %1; cvt.u32.u64 %0, t; }" : "=r"(a) : "l"(p));
    return a;
}
__device__ __forceinline__ void cp_async16(uint32_t dst, const void* src) {
    asm volatile("cp.async.cg.shared.global [%0], [%1], 16;" :: "r"(dst), "l"(src));
}
#define CP_COMMIT() asm volatile("cp.async.commit_group;" ::: "memory")
#define CP_WAIT(n)  asm volatile("cp.async.wait_group %0;" :: "n"(n) : "memory")

#define LDSM4(r0, r1, r2, r3, a)                                             \
    asm volatile("ldmatrix.sync.aligned.m8n8.x4.shared.b16 {%0,%1,%2,%3}, [%4];" \
                 : "=r"(r0), "=r"(r1), "=r"(r2), "=r"(r3) : "r"(a))

// fp16-accumulate MMA
__device__ __forceinline__ void mma16816_f16(uint32_t* c, const uint32_t* a, const uint32_t* b) {
    asm volatile(
        "mma.sync.aligned.m16n8k16.row.col.f16.f16.f16.f16 "
        "{%0,%1}, {%2,%3,%4,%5}, {%6,%7}, {%0,%1};"
        : "+r"(c[0]), "+r"(c[1])
        : "r"(a[0]), "r"(a[1]), "r"(a[2]), "r"(a[3]), "r"(b[0]), "r"(b[1]));
}

__device__ __forceinline__ uint32_t sw128(uint32_t off) { return off ^ ((off >> 3) & 0x70); }

// order-preserving float<->uint
__device__ __forceinline__ unsigned fmap(float v) {
    unsigned b = __float_as_uint(v);
    return (b & 0x80000000u) ? ~b : (b | 0x80000000u);
}
__device__ __forceinline__ float funmap(unsigned m) {
    unsigned b = (m & 0x80000000u) ? (m & 0x7FFFFFFFu) : ~m;
    return __uint_as_float(b);
}

// ---------------- fused prep: convert x/W to fp16, init rowmax, transpose Wg ---
#define NBX ((BATCH * KH / 4) / 256)          // 8192
#define NBW ((HID * KH / 4) / 256)            // 16384
#define NBT ((HID / 32) * ((NCLS + 31) / 32)) // 8192
__global__ __launch_bounds__(256)
void prep_kernel(const float* __restrict__ x, const float* __restrict__ Wk,
                 const float* __restrict__ Wg) {
    const int bid = blockIdx.x;
    const int tid = threadIdx.x;
    if (bid < NBX) {
        int i = bid * 256 + tid;
        if (i < BATCH) g_rowmax[i] = 0u;            // == -inf in mapped space
        float4 v = ((const float4*)x)[i];
        __half2 h0 = __floats2half2_rn(v.x, v.y);
        __half2 h1 = __floats2half2_rn(v.z, v.w);
        ((uint2*)g_X)[i] = make_uint2(*(unsigned*)&h0, *(unsigned*)&h1);
    } else if (bid < NBX + NBW) {
        int i = (bid - NBX) * 256 + tid;
        float4 v = ((const float4*)Wk)[i];
        __half2 h0 = __floats2half2_rn(v.x, v.y);
        __half2 h1 = __floats2half2_rn(v.z, v.w);
        ((uint2*)g_W)[i] = make_uint2(*(unsigned*)&h0, *(unsigned*)&h1);
    } else {
        // transpose Wg[NCLS][HID] -> g_WgT[HID][NCLS], 32x32 tiles, 256 threads
        __shared__ float t[32][33];
        int tb  = bid - (NBX + NBW);
        int h0  = (tb & 255) * 32;          // HID/32 = 256
        int c0  = (tb >> 8) * 32;
        int txx = tid & 31, ty = tid >> 5;  // ty: 0..7
#pragma unroll
        for (int r = 0; r < 4; r++) {
            int c = c0 + ty + r * 8;
            if (c < NCLS) t[ty + r * 8][txx] = Wg[(size_t)c * HID + h0 + txx];
        }
        __syncthreads();
#pragma unroll
        for (int r = 0; r < 4; r++) {
            int ho = h0 + ty + r * 8, co = c0 + txx;
            if (co < NCLS) g_WgT[(size_t)ho * NCLS + co] = t[txx][ty + r * 8];
        }
    }
}

// ---------------- pass 1: fp16 GEMM + fused row/tile max -----------------------
// CTA tile 256x128, 8 warps 4(m)x2(n), warp tile 64x64, 2-stage cp.async,
// 2 CTAs/SM, ONE barrier per chunk.
__global__ __launch_bounds__(256, 2)
void gemm_approx() {
    extern __shared__ char smem[];
    const int tid  = threadIdx.x;
    const int lane = tid & 31;
    const int wid  = tid >> 5;
    const int warp_m = wid >> 1;  // 0..3
    const int warp_n = wid & 1;   // 0..1

    int bid = blockIdx.x;
    int group = bid >> 7, within = bid & 127;
    int ncol = (group << 3) | (within & 7);   // 0..63
    int mrow = within >> 3;                   // 0..15
    const int bm0 = mrow * 256;
    const int bn0 = ncol * 128;

    uint32_t sb    = smem_u32(smem);
    uint32_t tiles = (sb + 1023) & ~1023u;

    const int row_l = tid >> 3;
    const int colb  = (tid & 7) * 16;
    uint32_t dswA[8];
#pragma unroll
    for (int i = 0; i < 8; i++) dswA[i] = sw128((row_l + 32 * i) * 128 + colb);

    const __half* pA = g_X + (size_t)(bm0 + row_l) * KH + (colb >> 1);
    const __half* pB = g_W + (size_t)(bn0 + row_l) * KH + (colb >> 1);

    const uint32_t aRow = warp_m * 64 + (lane & 15);
    const uint32_t aCol = (lane >> 4) << 4;
    const uint32_t bRow = warp_n * 64 + (lane & 7) + ((lane >> 4) << 3);
    const uint32_t bCol = ((lane >> 3) & 1) << 4;
    uint32_t aSwk[4], bSwk[4];
#pragma unroll
    for (int kk = 0; kk < 4; kk++) {
        aSwk[kk] = sw128(aRow * 128 + aCol + kk * 32);
        bSwk[kk] = sw128(bRow * 128 + bCol + kk * 32);
    }

    uint32_t acc[4][8][2];   // fp16x2 accumulators
#pragma unroll
    for (int i = 0; i < 4; i++)
#pragma unroll
        for (int j = 0; j < 8; j++) { acc[i][j][0] = 0u; acc[i][j][1] = 0u; }

    // prologue: issue chunk 0
    {
        uint32_t As = tiles;
        uint32_t Bs = As + 32768u;
#pragma unroll
        for (int i = 0; i < 8; i++) cp_async16(As + dswA[i], pA + (size_t)i * 32 * KH);
#pragma unroll
        for (int i = 0; i < 4; i++) cp_async16(Bs + dswA[i], pB + (size_t)i * 32 * KH);
        CP_COMMIT();
    }

    for (int c = 0; c < NCH; c++) {
        const int s = c & 1;

        CP_WAIT(0);
        __syncthreads();   // chunk c visible; all warps done with chunk c-1 (stage s^1)

        if (c + 1 < NCH) {
            uint32_t As = tiles + (s ^ 1) * STAGE_BYTES;
            uint32_t Bs = As + 32768u;
            size_t ko = (size_t)(c + 1) * 64;
#pragma unroll
            for (int i = 0; i < 8; i++) cp_async16(As + dswA[i], pA + (size_t)i * 32 * KH + ko);
#pragma unroll
            for (int i = 0; i < 4; i++) cp_async16(Bs + dswA[i], pB + (size_t)i * 32 * KH + ko);
            CP_COMMIT();
        }

        const uint32_t aBase = tiles + s * STAGE_BYTES;
        const uint32_t bBase = aBase + 32768u;

#pragma unroll
        for (int kk = 0; kk < 4; kk++) {
            uint32_t a[4][4];
#pragma unroll
            for (int im = 0; im < 4; im++)
                LDSM4(a[im][0], a[im][1], a[im][2], a[im][3],
                      aBase + aSwk[kk] + im * 2048u);
            uint32_t b[8][2];
#pragma unroll
            for (int in2 = 0; in2 < 4; in2++) {
                uint32_t r0, r1, r2, r3;
                LDSM4(r0, r1, r2, r3, bBase + bSwk[kk] + in2 * 2048u);
                b[2 * in2][0] = r0;     b[2 * in2][1] = r1;
                b[2 * in2 + 1][0] = r2; b[2 * in2 + 1][1] = r3;
            }
#pragma unroll
            for (int im = 0; im < 4; im++)
#pragma unroll
                for (int jn = 0; jn < 8; jn++)
                    mma16816_f16(acc[im][jn], a[im], b[jn]);
        }
        // no trailing sync: next iteration's top sync orders stage reuse
    }

    // ---- epilogue: store C + fused per-row / per-tile max ----
    __syncthreads();                       // all compute done; smem reusable
    unsigned* rmax = (unsigned*)smem;      // [256] per-CTA row maxima
    rmax[tid] = 0u;
    __syncthreads();

#pragma unroll
    for (int im = 0; im < 4; im++) {
        int rloc = warp_m * 64 + im * 16 + (lane >> 2);
        int r0 = bm0 + rloc;
        float m0 = -3.4e38f, m1 = -3.4e38f;
#pragma unroll
        for (int jn = 0; jn < 8; jn++) {
            int col = bn0 + warp_n * 64 + jn * 8 + (lane & 3) * 2;
            *(uint32_t*)&g_C[(size_t)r0 * HID + col]       = acc[im][jn][0];
            *(uint32_t*)&g_C[(size_t)(r0 + 8) * HID + col] = acc[im][jn][1];
            __half2 h0 = *(__half2*)&acc[im][jn][0];
            __half2 h1 = *(__half2*)&acc[im][jn][1];
            m0 = fmaxf(m0, fmaxf(__low2float(h0), __high2float(h0)));
            m1 = fmaxf(m1, fmaxf(__low2float(h1), __high2float(h1)));
        }
        atomicMax(&rmax[rloc],     fmap(m0));
        atomicMax(&rmax[rloc + 8], fmap(m1));
    }
    __syncthreads();
    // this CTA is the exclusive owner of (rows bm0..bm0+255, tile ncol)
    g_tmax[(size_t)(bm0 + tid) * 64 + ncol] = rmax[tid];
    atomicMax(&g_rowmax[bm0 + tid], rmax[tid]);
}

// ---------------- pass 2: screen + (fast path | exact refine) + gather ---------
__global__ __launch_bounds__(256)
void refine_kernel(const float* __restrict__ x, const float* __restrict__ Wk,
                   float* __restrict__ out) {
    __shared__ float4 xs4[IN / 4];    // 8KB: row of x (loaded ONLY if nc > 1)
    __shared__ float red8[8];
    __shared__ float tot_s;
    __shared__ int   cand[MAXCAND];
    __shared__ int   tlist[64];
    __shared__ int   ncand, ntl, best_s;

    const int b    = blockIdx.x;
    const int tid  = threadIdx.x;
    const int lane = tid & 31;
    const int wid  = tid >> 5;

    if (tid == 0) { ncand = 0; ntl = 0; }
    const float thr = funmap(g_rowmax[b]) - MARGIN;
    __syncthreads();

    // screen 64 tile maxima
    if (tid < 64) {
        if (funmap(g_tmax[(size_t)b * 64 + tid]) >= thr) {
            int p = atomicAdd(&ntl, 1);
            tlist[p] = tid;
        }
    }
    __syncthreads();
    const int nt = ntl;

    // scan only promising tiles for candidate columns
    for (int ti = 0; ti < nt; ti++) {
        const int t = tlist[ti];
        if (tid < 64) {
            __half2 v = *(const __half2*)(g_C + (size_t)b * HID + t * 128 + 2 * tid);
            float a = __low2float(v), c = __high2float(v);
            if (a >= thr) { int p = atomicAdd(&ncand, 1); if (p < MAXCAND) cand[p] = t * 128 + 2 * tid; }
            if (c >= thr) { int p = atomicAdd(&ncand, 1); if (p < MAXCAND) cand[p] = t * 128 + 2 * tid + 1; }
        }
    }
    __syncthreads();
    const int nc = min(ncand, MAXCAND);

    if (nc == 1) {
        // fast path (~61% of rows): sole candidate IS the argmax; no dots needed
        if (tid == 0) best_s = cand[0];
    } else {
        // slow path: exact fp32 dot per candidate, block-wide
        const float4* xrow = (const float4*)(x + (size_t)b * IN);
        for (int i = tid; i < IN / 4; i += 256) xs4[i] = xrow[i];
        __syncthreads();

        float bestv = -3.4e38f;
        int   besti = HID;
        for (int ci = 0; ci < nc; ci++) {
            const int h = cand[ci];
            const float4* wr = (const float4*)(Wk + (size_t)h * IN);
            float p = 0.0f;
            for (int k = tid; k < IN / 4; k += 256) {
                float4 xv = xs4[k], wv = wr[k];
                p = fmaf(xv.x, wv.x, p); p = fmaf(xv.y, wv.y, p);
                p = fmaf(xv.z, wv.z, p); p = fmaf(xv.w, wv.w, p);
            }
#pragma unroll
            for (int o = 16; o > 0; o >>= 1) p += __shfl_xor_sync(0xffffffffu, p, o);
            if (lane == 0) red8[wid] = p;
            __syncthreads();
            if (tid == 0) {
                float t = 0.0f;
#pragma unroll
                for (int i = 0; i < 8; i++) t += red8[i];
                tot_s = t;
            }
            __syncthreads();
            float tot = tot_s;
            if (tot > bestv || (tot == bestv && h < besti)) { bestv = tot; besti = h; }
            __syncthreads();   // red8/tot_s reuse
        }
        if (tid == 0) best_s = besti;
    }
    __syncthreads();

    // fused output gather: out[b][:] = WgT[best][:]  (4000B rows, 16B aligned)
    const float4* src = (const float4*)(g_WgT + (size_t)best_s * NCLS);
    float4* dst = (float4*)(out + (size_t)b * NCLS);
    for (int c = tid; c < NCLS / 4; c += 256) dst[c] = src[c];
}

// ---------------- launch --------------------------------------------------------
extern "C" void kernel_launch(void* const* d_in, const int* in_sizes, int n_in,
                              void* d_out, int out_size) {
    const float* x  = (const float*)d_in[0];   // [BATCH, IN]
    const float* Wk = (const float*)d_in[1];   // [HID, IN]
    const float* Wg = (const float*)d_in[2];   // [NCLS, HID]
    float* out = (float*)d_out;                // [BATCH, NCLS]

    const int SMEM_BYTES = 1024 + ST * (int)STAGE_BYTES;   // ~97KB per CTA
    cudaFuncSetAttribute(gemm_approx, cudaFuncAttributeMaxDynamicSharedMemorySize, SMEM_BYTES);

    prep_kernel<<<NBX + NBW + NBT, 256>>>(x, Wk, Wg);

    gemm_approx<<<(BATCH / 256) * (HID / 128), 256, SMEM_BYTES>>>();

    refine_kernel<<<BATCH, 256>>>(x, Wk, out);
}